// round 1
// baseline (speedup 1.0000x reference)
#include <cuda_runtime.h>
#include <cstdint>
#include <cstddef>

// BlockSparseLinear: out[8192,4096] = x[8192,4096] @ (W .* mask)^T + bias
// Shapes fixed by the problem.
#define M_TOTAL 8192
#define KDIM    4096
#define NDIM    4096
#define NB      256      // 16-wide blocks along K (and along OUT)

// ---------------- device scratch (no allocations allowed) ----------------
__device__ int            g_flagmask;         // mask dtype detection flags
__device__ int            g_nblk[NB];         // active K-blocks per out-block
__device__ unsigned char  g_blist[NB][NB];    // compacted K-block indices

// ---------------- 0) reset detection flags (graph replays!) --------------
__global__ void init_kernel() {
    if (threadIdx.x == 0) g_flagmask = 0;
}

// ---------------- 1) detect mask dtype by bit pattern ---------------------
// Scans the first 1M 32-bit words (4 MB) of the mask buffer. The mask is
// 16x16 block structured with ~10% density, so every plausible dtype leaves
// an unambiguous signature in this window:
//   f32  1.0          -> word 0x3F800000
//   bf16 (1.0,1.0)    -> word 0x3F803F80  (runs of 16 guarantee aligned pairs)
//   bool bytes (runs) -> word 0x01010101  (runs of 16 guarantee full words)
//   int32 1           -> word 0x00000001
__global__ void detect_kernel(const unsigned int* __restrict__ m) {
    unsigned int w = m[(size_t)blockIdx.x * blockDim.x + threadIdx.x];
    unsigned int f = 0u;
    if (w == 0x3F800000u) f |= 1u;   // float32
    if (w == 0x3F803F80u) f |= 2u;   // bfloat16
    if (w == 0x01010101u) f |= 4u;   // bool bytes
    if (w == 0x00000001u) f |= 8u;   // int32
    f = __reduce_or_sync(0xFFFFFFFFu, f);
    __shared__ unsigned int sf;
    if (threadIdx.x == 0) sf = 0u;
    __syncthreads();
    if ((threadIdx.x & 31) == 0 && f) atomicOr(&sf, f);
    __syncthreads();
    if (threadIdx.x == 0 && sf) atomicOr((unsigned int*)&g_flagmask, (int)sf);
}

// ---------------- 2) build per-out-block active K-block lists -------------
// The mask is exactly block-constant (jnp.repeat of a block mask), so one
// element per 16x16 block decides activity. Ordered compaction by thread 0
// keeps summation order (and thus output bits) deterministic.
__global__ void build_kernel(const void* __restrict__ mask) {
    int ob = blockIdx.x;       // out-block 0..255
    int kb = threadIdx.x;      // K-block   0..255
    int fl = g_flagmask;
    size_t e = (size_t)(ob * 16) * KDIM + (size_t)kb * 16;  // element index
    bool a;
    if (fl & 1)       a = ((const float*)mask)[e] != 0.0f;
    else if (fl & 2)  a = ((const unsigned short*)mask)[e] != 0;
    else if (fl & 4)  a = ((const unsigned char*)mask)[e]  != 0;
    else              a = ((const int*)mask)[e]            != 0;

    __shared__ unsigned char act[NB];
    act[kb] = a ? 1 : 0;
    __syncthreads();
    if (kb == 0) {
        int n = 0;
        #pragma unroll 1
        for (int k = 0; k < NB; k++)
            if (act[k]) g_blist[ob][n++] = (unsigned char)k;
        g_nblk[ob] = n;
    }
}

// ---------------- 3) block-sparse GEMM ------------------------------------
// CTA tile: 128 rows (M) x 16 cols (one out-block). 256 threads.
// tx = out col within block (0..15), ty = 8-row group (0..15).
// Each thread accumulates 8 outputs. Loop over active K-blocks only.
// Grid: x = out-block (fast) so the 2 MB x row-tile stays L2-resident
// across all 256 out-blocks; y = M tile.
__global__ __launch_bounds__(256) void gemm_kernel(
    const float* __restrict__ x, const float* __restrict__ w,
    const float* __restrict__ bias, float* __restrict__ out)
{
    __shared__ float xs[16][132];   // K-major x tile; pad 132 keeps 16B align + few conflicts
    __shared__ float ws[16][17];    // W block, pad 17 -> conflict-free
    __shared__ unsigned char bl[NB];

    int ob  = blockIdx.x;
    int m0  = blockIdx.y * 128;
    int tid = threadIdx.x;
    int tx  = tid & 15;
    int ty  = tid >> 4;

    int nblk = g_nblk[ob];
    bl[tid]  = g_blist[ob][tid];

    int lrow = tid >> 1;            // 0..127 : row this thread loads
    int lq   = (tid & 1) * 8;       // which 8 floats of the 16-wide slice

    float acc[8];
    #pragma unroll
    for (int r = 0; r < 8; r++) acc[r] = 0.0f;

    __syncthreads();                // bl[] visible

    for (int it = 0; it < nblk; it++) {
        int kc = (int)bl[it] * 16;

        // W block: 256 threads, 1 element each, k fastest -> coalesced
        {
            int k = tid & 15, n = tid >> 4;
            ws[k][n] = w[(size_t)(ob * 16 + n) * KDIM + kc + k];
        }
        // x tile: 2 float4 per thread, transpose into K-major smem
        {
            const float4* xp = (const float4*)(x + (size_t)(m0 + lrow) * KDIM + kc + lq);
            float4 v0 = xp[0], v1 = xp[1];
            xs[lq + 0][lrow] = v0.x; xs[lq + 1][lrow] = v0.y;
            xs[lq + 2][lrow] = v0.z; xs[lq + 3][lrow] = v0.w;
            xs[lq + 4][lrow] = v1.x; xs[lq + 5][lrow] = v1.y;
            xs[lq + 6][lrow] = v1.z; xs[lq + 7][lrow] = v1.w;
        }
        __syncthreads();

        #pragma unroll
        for (int k = 0; k < 16; k++) {
            float  wv = ws[k][tx];
            float4 xa = *(const float4*)&xs[k][ty * 8];
            float4 xb = *(const float4*)&xs[k][ty * 8 + 4];
            acc[0] += xa.x * wv; acc[1] += xa.y * wv;
            acc[2] += xa.z * wv; acc[3] += xa.w * wv;
            acc[4] += xb.x * wv; acc[5] += xb.y * wv;
            acc[6] += xb.z * wv; acc[7] += xb.w * wv;
        }
        __syncthreads();
    }

    float  bv   = bias[ob * 16 + tx];
    size_t ocol = (size_t)ob * 16 + tx;
    #pragma unroll
    for (int r = 0; r < 8; r++)
        out[(size_t)(m0 + ty * 8 + r) * NDIM + ocol] = acc[r] + bv;
}

// ---------------- launch ---------------------------------------------------
extern "C" void kernel_launch(void* const* d_in, const int* in_sizes, int n_in,
                              void* d_out, int out_size)
{
    const float* x    = (const float*)d_in[0];
    const float* w    = (const float*)d_in[1];
    const float* bias = (const float*)d_in[2];
    const void*  mask = d_in[3];
    float*       out  = (float*)d_out;

    init_kernel<<<1, 32>>>();
    detect_kernel<<<4096, 256>>>((const unsigned int*)mask);   // 1M words = 4MB window
    build_kernel<<<NB, NB>>>(mask);
    gemm_kernel<<<dim3(NB, M_TOTAL / 128), 256>>>(x, w, bias, out);
}

// round 9
// speedup vs baseline: 1.7906x; 1.7906x over previous
#include <cuda_runtime.h>
#include <cuda_bf16.h>
#include <cstdint>
#include <cstddef>

// out[8192,4096] = x[8192,4096] @ (W .* mask)^T + bias  (fp32 in/out)
// Warp-level mma.sync (HMMA) bf16 with hi/lo split compensation, fp32 accum.
// Portable PTX (sm_80+): identical code in both compiler passes, no tcgen05.
#define MTOT 8192
#define KDIM 4096
#define NDIM 4096
#define NBK  256       // 16-wide K blocks
#define NGRP 32        // groups of 8 out-blocks (128 cols each)

// ---------------- device scratch ----------------
__device__ int           g_flagmask;
__device__ int           g_kn[NGRP];
__device__ unsigned char g_klist[NGRP][NBK];  // compacted active kb indices
__device__ unsigned char g_actL[NGRP][NBK];   // 8-bit ob activity, list order

// ---------------- smem layout (static, 25.1KB) ----------------
// xs hi: [128 rows][48B] at 0 ; xs lo at 6144
// ws:    [8 obs][hi 16x48B | lo 16x48B] at 12288 (1536 per ob)
// bias:  128 floats at 24576
#define SMX_LO  6144
#define SMW     12288
#define SMBIAS  24576
#define SMSZ    25088

static __device__ __forceinline__ uint32_t s2u(const void* p) {
    uint32_t a;
    asm("{ .reg .u64 t; cvta.to.shared.u64 t, %1; cvt.u32.u64 %0, t; }" : "=r"(a) : "l"(p));
    return a;
}
// 8 floats -> 8 bf16 hi (uint4) + 8 bf16 lo (uint4)
static __device__ __forceinline__ void split8(float4 v0, float4 v1, uint4& hi, uint4& lo) {
    float f[8] = {v0.x, v0.y, v0.z, v0.w, v1.x, v1.y, v1.z, v1.w};
    unsigned h[8], l[8];
    #pragma unroll
    for (int i = 0; i < 8; i++) {
        __nv_bfloat16 hb = __float2bfloat16(f[i]);
        float r = f[i] - __bfloat162float(hb);
        __nv_bfloat16 lb = __float2bfloat16(r);
        h[i] = (unsigned)__bfloat16_as_ushort(hb);
        l[i] = (unsigned)__bfloat16_as_ushort(lb);
    }
    hi = make_uint4(h[0] | (h[1] << 16), h[2] | (h[3] << 16), h[4] | (h[5] << 16), h[6] | (h[7] << 16));
    lo = make_uint4(l[0] | (l[1] << 16), l[2] | (l[3] << 16), l[4] | (l[5] << 16), l[6] | (l[7] << 16));
}

#define LDSM_X4(r, addr) \
    asm volatile("ldmatrix.sync.aligned.m8n8.x4.shared.b16 {%0,%1,%2,%3}, [%4];" \
        : "=r"((r)[0]), "=r"((r)[1]), "=r"((r)[2]), "=r"((r)[3]) : "r"(addr))
#define LDSM_X2(r, addr) \
    asm volatile("ldmatrix.sync.aligned.m8n8.x2.shared.b16 {%0,%1}, [%2];" \
        : "=r"((r)[0]), "=r"((r)[1]) : "r"(addr))
#define MMA16816(c, A, B) \
    asm volatile("mma.sync.aligned.m16n8k16.row.col.f32.bf16.bf16.f32 " \
        "{%0,%1,%2,%3},{%4,%5,%6,%7},{%8,%9},{%0,%1,%2,%3};" \
        : "+f"((c)[0]), "+f"((c)[1]), "+f"((c)[2]), "+f"((c)[3]) \
        : "r"((A)[0]), "r"((A)[1]), "r"((A)[2]), "r"((A)[3]), "r"((B)[0]), "r"((B)[1]))

// ---------------- 0) reset flags ----------------
__global__ void init_kernel() { if (threadIdx.x == 0) g_flagmask = 0; }

// ---------------- 1) mask dtype detection (4MB window) ----------------
__global__ void detect_kernel(const unsigned int* __restrict__ m) {
    unsigned int w = m[(size_t)blockIdx.x * blockDim.x + threadIdx.x];
    unsigned int f = 0u;
    if (w == 0x3F800000u) f |= 1u;   // float32 1.0
    if (w == 0x3F803F80u) f |= 2u;   // bf16 (1.0,1.0)
    if (w == 0x01010101u) f |= 4u;   // bool byte run
    if (w == 0x00000001u) f |= 8u;   // int32 1
    f = __reduce_or_sync(0xFFFFFFFFu, f);
    __shared__ unsigned int sf;
    if (threadIdx.x == 0) sf = 0u;
    __syncthreads();
    if ((threadIdx.x & 31) == 0 && f) atomicOr(&sf, f);
    __syncthreads();
    if (threadIdx.x == 0 && sf) atomicOr((unsigned int*)&g_flagmask, (int)sf);
}

// ---------------- 2) build compacted activity lists ----------------
__global__ void build_kernel(const void* __restrict__ mask) {
    int g = blockIdx.x, kb = threadIdx.x;
    int fl = g_flagmask;
    unsigned m = 0;
    for (int a = 0; a < 8; a++) {
        size_t e = (size_t)((g * 8 + a) * 16) * KDIM + (size_t)kb * 16;
        bool v;
        if (fl & 1)      v = ((const float*)mask)[e] != 0.0f;
        else if (fl & 2) v = ((const unsigned short*)mask)[e] != 0;
        else if (fl & 4) v = ((const unsigned char*)mask)[e] != 0;
        else             v = ((const int*)mask)[e] != 0;
        if (v) m |= 1u << a;
    }
    __shared__ unsigned sact[NBK];
    sact[kb] = m;
    __syncthreads();
    if (kb == 0) {
        int n = 0;
        #pragma unroll 1
        for (int k = 0; k < NBK; k++) {
            if (sact[k]) {
                g_klist[g][n] = (unsigned char)k;
                g_actL[g][n]  = (unsigned char)sact[k];
                n++;
            }
        }
        g_kn[g] = n;
    }
}

// ---------------- 3) block-sparse HMMA GEMM ----------------
// CTA: 128 M rows x 128 N cols (8 obs). Warp w: rows w*16..w*16+15, all obs.
// Per active kb: stage x + active W (bf16 hi/lo, stride-48 smem), ldmatrix
// fragments, per-ob 6 mma.sync (2 n8 tiles x {hh, lh, hl}).
__global__ void __launch_bounds__(256, 2) gemm_kernel(
    const float* __restrict__ x, const float* __restrict__ wt,
    const float* __restrict__ bias, float* __restrict__ out)
{
    __shared__ __align__(16) char smem[SMSZ];
    uint32_t sbase = s2u(smem);
    int tid = threadIdx.x, w = tid >> 5, lane = tid & 31;
    int g = blockIdx.x, m0 = blockIdx.y << 7;

    if (tid < 128) ((float*)(smem + SMBIAS))[tid] = bias[g * 128 + tid];
    __syncthreads();

    float C[8][2][4];
    #pragma unroll
    for (int a = 0; a < 8; a++)
        #pragma unroll
        for (int nt = 0; nt < 2; nt++)
            #pragma unroll
            for (int q = 0; q < 4; q++) C[a][nt][q] = 0.0f;

    int kn = g_kn[g];
    // x staging: thread -> (row tid>>1, half tid&1)
    const float* xrow = x + (size_t)(m0 + (tid >> 1)) * KDIM + (tid & 1) * 8;
    // W staging: warp w owns ob w; lane -> (row lane>>1, half lane&1)
    const float* wrow = wt + (size_t)((g * 8 + w) * 16 + (lane >> 1)) * KDIM + (lane & 1) * 8;

    float4 xp0, xp1, wp0, wp1;
    if (kn > 0) {
        int kb = g_klist[g][0];
        const float4* p = (const float4*)(xrow + kb * 16);
        xp0 = __ldg(p); xp1 = __ldg(p + 1);
        if ((g_actL[g][0] >> w) & 1) {
            const float4* q = (const float4*)(wrow + kb * 16);
            wp0 = __ldg(q); wp1 = __ldg(q + 1);
        }
    }

    // A-fragment ldmatrix address pieces (per validated m8n8.x4 convention):
    // lanes 0-7: rows 0-7 k0-7 | 8-15: rows 8-15 k0-7 | 16-23: rows 0-7 k8-15 | 24-31: rows 8-15 k8-15
    int arow = (lane & 7) + ((lane & 8) ? 8 : 0);
    int acb  = (lane & 16) ? 16 : 0;
    uint32_t a_addr = sbase + (uint32_t)((w * 16 + arow) * 48 + acb);

    for (int i = 0; i < kn; i++) {
        unsigned act = g_actL[g][i];

        // ---- stage x tile ----
        {
            uint4 hi, lo; split8(xp0, xp1, hi, lo);
            int row = tid >> 1, half = tid & 1;
            *(uint4*)(smem + row * 48 + half * 16)           = hi;
            *(uint4*)(smem + SMX_LO + row * 48 + half * 16)  = lo;
        }
        // ---- stage W block (warp w's ob, if active) ----
        if ((act >> w) & 1) {
            uint4 hi, lo; split8(wp0, wp1, hi, lo);
            int row = lane >> 1, half = lane & 1;
            char* base = smem + SMW + w * 1536;
            *(uint4*)(base + row * 48 + half * 16)        = hi;
            *(uint4*)(base + 768 + row * 48 + half * 16)  = lo;
        }
        // ---- prefetch next active kb (overlaps MMAs below) ----
        if (i + 1 < kn) {
            int kb = g_klist[g][i + 1];
            const float4* p = (const float4*)(xrow + kb * 16);
            xp0 = __ldg(p); xp1 = __ldg(p + 1);
            if ((g_actL[g][i + 1] >> w) & 1) {
                const float4* q = (const float4*)(wrow + kb * 16);
                wp0 = __ldg(q); wp1 = __ldg(q + 1);
            }
        }
        __syncthreads();

        // ---- A fragments (hi, lo) ----
        unsigned ah[4], al[4];
        LDSM_X4(ah, a_addr);
        LDSM_X4(al, a_addr + SMX_LO);

        // ---- per-ob B fragments + MMAs ----
        #pragma unroll
        for (int a = 0; a < 8; a++) {
            if ((act >> a) & 1) {
                uint32_t wb = sbase + SMW + a * 1536;
                #pragma unroll
                for (int nt = 0; nt < 2; nt++) {
                    uint32_t baddr = wb + (uint32_t)((nt * 8 + (lane & 7)) * 48 + ((lane & 8) ? 16 : 0));
                    unsigned bh[2], bl[2];
                    LDSM_X2(bh, baddr);
                    LDSM_X2(bl, baddr + 768);
                    MMA16816(C[a][nt], ah, bh);
                    MMA16816(C[a][nt], al, bh);
                    MMA16816(C[a][nt], ah, bl);
                }
            }
        }
        __syncthreads();
    }

    // ---- epilogue: bias + store (fragment layout: r = lane>>2, c = 2*(lane&3)) ----
    {
        int r0 = m0 + w * 16 + (lane >> 2);
        int c0 = (lane & 3) * 2;
        const float* sbias = (const float*)(smem + SMBIAS);
        #pragma unroll
        for (int a = 0; a < 8; a++) {
            #pragma unroll
            for (int nt = 0; nt < 2; nt++) {
                int col = a * 16 + nt * 8 + c0;
                float b0 = sbias[col], b1 = sbias[col + 1];
                size_t gc = (size_t)g * 128 + col;
                float2 v0 = make_float2(C[a][nt][0] + b0, C[a][nt][1] + b1);
                float2 v1 = make_float2(C[a][nt][2] + b0, C[a][nt][3] + b1);
                *(float2*)(out + (size_t)r0 * NDIM + gc)       = v0;
                *(float2*)(out + (size_t)(r0 + 8) * NDIM + gc) = v1;
            }
        }
    }
}

// ---------------- launch ----------------
extern "C" void kernel_launch(void* const* d_in, const int* in_sizes, int n_in,
                              void* d_out, int out_size)
{
    const float* x    = (const float*)d_in[0];
    const float* wt   = (const float*)d_in[1];
    const float* bias = (const float*)d_in[2];
    const void*  mask = d_in[3];
    float*       out  = (float*)d_out;

    init_kernel<<<1, 32>>>();
    detect_kernel<<<4096, 256>>>((const unsigned int*)mask);
    build_kernel<<<NGRP, NBK>>>(mask);
    gemm_kernel<<<dim3(NGRP, MTOT / 128), 256>>>(x, wt, bias, out);
}